// round 3
// baseline (speedup 1.0000x reference)
#include <cuda_runtime.h>
#include <math.h>

// Problem dims
#define BB   256
#define TT   1024
#define FF   64
#define EE   256
#define GG   1024      // 4*E
#define KENC 320       // F + E
#define KDEC 256       // E (decoder input composed into Whh)

// Persistent-kernel tiling
#define NCTA 128
#define MB   32        // batch rows per CTA   (8 batch tiles)
#define NE   16        // e-units per CTA      (16 e tiles)
#define STH  128
#define ASTR 324       // A smem row stride (pad: tm*324 %32 = tm*4 -> spread banks)
#define WSTR 68        // W smem row stride [k][c]

// Projection tiling
#define PM   64

typedef unsigned long long u64;

// ---------------- device scratch (static: no allocation) ----------------
__device__ float g_h[2][BB * EE];                    // ping-pong hidden state
__device__ float g_Wenc[GG * KENC];                  // [Wih | Whh] rows, K=320
__device__ float g_benc[GG];                         // bih + bhh
__device__ float g_Wdec[GG * KDEC];                  // dWhh + dWih @ Wd
__device__ float g_bdec[GG];                         // dbih + dbhh + dWih @ bd
__device__ float g_Hall[(size_t)TT * BB * EE];       // all decoder h_t (256 MB)
__device__ unsigned g_arrive;
__device__ volatile unsigned g_gen;

__device__ __forceinline__ float sigmoidf_(float v) { return 1.0f / (1.0f + expf(-v)); }

// ---- packed f32x2 helpers (Blackwell FFMA2) ----
__device__ __forceinline__ u64 pack2_dup(float a) {
    u64 r; unsigned u = __float_as_uint(a);
    asm("mov.b64 %0, {%1, %2};" : "=l"(r) : "r"(u), "r"(u));
    return r;
}
__device__ __forceinline__ void fma2(u64& d, u64 a, u64 b) {
    asm("fma.rn.f32x2 %0, %1, %2, %3;" : "=l"(d) : "l"(a), "l"(b), "l"(d));
}
__device__ __forceinline__ float2 unpack2(u64 v) {
    unsigned lo, hi;
    asm("mov.b64 {%0, %1}, %2;" : "=r"(lo), "=r"(hi) : "l"(v));
    float2 r; r.x = __uint_as_float(lo); r.y = __uint_as_float(hi); return r;
}

// ---------------- init ----------------
__global__ void init_state() {
    int i = blockIdx.x * blockDim.x + threadIdx.x;
    if (i < BB * EE) g_h[0][i] = 0.0f;
    if (i == 0) { g_arrive = 0; g_gen = 0; }
}

// ---------------- weight packing / decoder composition ----------------
__global__ void pack_weights(const float* __restrict__ eWih, const float* __restrict__ eWhh,
                             const float* __restrict__ ebih, const float* __restrict__ ebhh,
                             const float* __restrict__ dWih, const float* __restrict__ dWhh,
                             const float* __restrict__ dbih, const float* __restrict__ dbhh,
                             const float* __restrict__ Wd,   const float* __restrict__ bd) {
    int row = blockIdx.x;          // 0..1023 (gate row)
    int tid = threadIdx.x;

    // encoder: concat [Wih | Whh] along K
    for (int k = tid; k < KENC; k += blockDim.x)
        g_Wenc[row * KENC + k] = (k < FF) ? eWih[row * FF + k] : eWhh[row * EE + (k - FF)];

    // decoder: Wcomb = dWhh + dWih @ Wd   (exact: x_t always = h@Wd^T + bd)
    for (int k = tid; k < KDEC; k += blockDim.x) {
        float s = dWhh[row * EE + k];
        #pragma unroll
        for (int f = 0; f < FF; f++) s += dWih[row * FF + f] * Wd[f * EE + k];
        g_Wdec[row * KDEC + k] = s;
    }
    if (tid == 0) {
        g_benc[row] = ebih[row] + ebhh[row];
        float s = dbih[row] + dbhh[row];
        for (int f = 0; f < FF; f++) s += dWih[row * FF + f] * bd[f];
        g_bdec[row] = s;
    }
}

// ---------------- software grid barrier (all 128 CTAs resident) ----------------
__device__ __forceinline__ void grid_sync(unsigned& gen) {
    __threadfence();            // publish this thread's h stores
    __syncthreads();
    if (threadIdx.x == 0) {
        unsigned t = atomicAdd(&g_arrive, 1u);
        if (t == NCTA - 1) {
            g_arrive = 0;
            __threadfence();
            g_gen = gen + 1;    // release
        } else {
            while (g_gen == gen) { }
            __threadfence();    // acquire
        }
    }
    gen++;
    __syncthreads();
}

// ---------------- stage this CTA's 64 W rows (transposed) into smem ----------------
template<int K>
__device__ __forceinline__ void stage_W(float* Ws, const float* __restrict__ gW, int e0) {
    int tid  = threadIdx.x;
    int c    = tid >> 1;                 // 0..63 gate-col
    int half = tid & 1;
    int wrow = (c >> 4) * EE + e0 + (c & 15);
    const float* src = gW + (size_t)wrow * K + half * (K / 2);
    #pragma unroll
    for (int k = 0; k < K / 2; k += 4) {
        float4 v = *(const float4*)(src + k);
        int kk = half * (K / 2) + k;
        Ws[(kk + 0) * WSTR + c] = v.x;
        Ws[(kk + 1) * WSTR + c] = v.y;
        Ws[(kk + 2) * WSTR + c] = v.z;
        Ws[(kk + 3) * WSTR + c] = v.w;
    }
}

// ---------------- one LSTM step (inlined in persistent loop) ----------------
template<int K, bool ENC>
__device__ __forceinline__ void do_step(
    const float* __restrict__ Ws, float* __restrict__ As,
    const float* __restrict__ x, int t, int rp,
    int b0, int e0, int tm, int tn,
    const float2* __restrict__ bi, float2* __restrict__ cc,
    int hall_t, unsigned& gen)
{
    const float* __restrict__ hr = g_h[rp];
    float*       __restrict__ hw = g_h[rp ^ 1];
    const int tid = threadIdx.x;

    // ---- stage A tile ----
    if (ENC) {
        #pragma unroll
        for (int j = 0; j < 4; j++) {                 // x_t slice: 32 x 64
            int fi = tid + STH * j;
            int row = fi >> 4, c4 = (fi & 15) * 4;
            float4 v = *(const float4*)(x + (size_t)(b0 + row) * (TT * FF) + (size_t)t * FF + c4);
            *(float4*)&As[row * ASTR + c4] = v;
        }
    }
    const int AOFF = ENC ? FF : 0;
    #pragma unroll
    for (int j = 0; j < 16; j++) {                    // h: 32 x 256, L2-coherent reads
        int fi = tid + STH * j;
        int row = fi >> 6, c4 = (fi & 63) * 4;
        float4 v = __ldcg((const float4*)(hr + (b0 + row) * EE + c4));
        *(float4*)&As[row * ASTR + AOFF + c4] = v;
    }
    __syncthreads();

    // ---- gates GEMM: 2 rows x (2e x 4 gates), f32x2 packed ----
    u64 acc[2][4];
    #pragma unroll
    for (int i = 0; i < 2; i++)
        #pragma unroll
        for (int g = 0; g < 4; g++) acc[i][g] = 0ull;

    const float* __restrict__ a0p = As + tm * ASTR;
    const float* __restrict__ a1p = As + (tm + 16) * ASTR;
    const float* __restrict__ wp  = Ws + 2 * tn;

    #pragma unroll 8
    for (int k = 0; k < K; k++) {
        u64 a0 = pack2_dup(a0p[k]);
        u64 a1 = pack2_dup(a1p[k]);
        const float* w = wp + k * WSTR;
        u64 b0v = *(const u64*)(w);
        u64 b1v = *(const u64*)(w + 16);
        u64 b2v = *(const u64*)(w + 32);
        u64 b3v = *(const u64*)(w + 48);
        fma2(acc[0][0], a0, b0v);  fma2(acc[1][0], a1, b0v);
        fma2(acc[0][1], a0, b1v);  fma2(acc[1][1], a1, b1v);
        fma2(acc[0][2], a0, b2v);  fma2(acc[1][2], a1, b2v);
        fma2(acc[0][3], a0, b3v);  fma2(acc[1][3], a1, b3v);
    }

    // ---- pointwise LSTM update; c lives in registers across all steps ----
    const int e = e0 + 2 * tn;
    #pragma unroll
    for (int i = 0; i < 2; i++) {
        const int b = b0 + tm + 16 * i;
        float2 vi = unpack2(acc[i][0]); vi.x += bi[0].x; vi.y += bi[0].y;
        float2 vf = unpack2(acc[i][1]); vf.x += bi[1].x; vf.y += bi[1].y;
        float2 vg = unpack2(acc[i][2]); vg.x += bi[2].x; vg.y += bi[2].y;
        float2 vo = unpack2(acc[i][3]); vo.x += bi[3].x; vo.y += bi[3].y;
        float ix = sigmoidf_(vi.x), iy = sigmoidf_(vi.y);
        float fx = sigmoidf_(vf.x), fy = sigmoidf_(vf.y);
        float gx = tanhf(vg.x),     gy = tanhf(vg.y);
        float ox = sigmoidf_(vo.x), oy = sigmoidf_(vo.y);
        cc[i].x = fx * cc[i].x + ix * gx;
        cc[i].y = fy * cc[i].y + iy * gy;
        float2 hv;
        hv.x = ox * tanhf(cc[i].x);
        hv.y = oy * tanhf(cc[i].y);
        *(float2*)(hw + b * EE + e) = hv;
        if (hall_t >= 0)
            *(float2*)(g_Hall + (size_t)hall_t * BB * EE + b * EE + e) = hv;
    }

    grid_sync(gen);
}

// ---------------- the persistent recurrence kernel ----------------
__global__ void __launch_bounds__(STH, 1)
persistent_kernel(const float* __restrict__ x)
{
    extern __shared__ float smem[];
    float* Ws = smem;                       // [K][WSTR], max 320*68
    float* As = smem + KENC * WSTR;         // [32][ASTR]

    const int tid = threadIdx.x;
    const int cta = blockIdx.x;             // 0..127
    const int b0  = (cta & 7) * MB;
    const int e0  = (cta >> 3) * NE;
    const int tn  = tid & 7;
    const int tm  = tid >> 3;
    const int e   = e0 + 2 * tn;

    unsigned gen = 0;
    float2 cc[2] = {{0.f, 0.f}, {0.f, 0.f}};
    float2 bi[4];

    // ===== encoder phase =====
    #pragma unroll
    for (int g = 0; g < 4; g++) bi[g] = *(const float2*)(g_benc + g * EE + e);
    stage_W<KENC>(Ws, g_Wenc, e0);
    __syncthreads();

    for (int t = 0; t < TT; t++)
        do_step<KENC, true>(Ws, As, x, t, t & 1, b0, e0, tm, tn, bi, cc,
                            (t == TT - 1) ? 0 : -1, gen);

    // ===== decoder phase (projection composed into Whh) =====
    #pragma unroll
    for (int g = 0; g < 4; g++) bi[g] = *(const float2*)(g_bdec + g * EE + e);
    stage_W<KDEC>(Ws, g_Wdec, e0);
    __syncthreads();

    for (int t = 1; t < TT; t++)
        do_step<KDEC, false>(Ws, As, nullptr, 0, (t - 1) & 1, b0, e0, tm, tn, bi, cc,
                             t, gen);
}

// ---------------- final projection: out = Hall @ Wd^T + bd ----------------
// out[(t*B+b)*F + f]  — exactly d_out's flat layout (reshape never moves data)
__global__ void __launch_bounds__(256)
project(const float* __restrict__ Wd, const float* __restrict__ bd,
        float* __restrict__ out) {
    __shared__ __align__(16) float Hs[PM][32 + 4];
    __shared__ __align__(16) float Ws[32][FF + 4];

    const int tid = threadIdx.x;
    const size_t m0 = (size_t)blockIdx.x * PM;
    const int tf = tid & 15;
    const int tm = tid >> 4;

    float acc[4][4];
    #pragma unroll
    for (int i = 0; i < 4; i++)
        #pragma unroll
        for (int j = 0; j < 4; j++) acc[i][j] = 0.0f;

    const int h_row = tid >> 2;
    const int h_q   = (tid & 3) * 8;
    const int w_f   = tid >> 2;
    const int w_q   = (tid & 3) * 8;

    for (int k0 = 0; k0 < EE; k0 += 32) {
        const float* hsrc = g_Hall + (m0 + h_row) * EE + k0 + h_q;
        *(float4*)&Hs[h_row][h_q]     = *(const float4*)(hsrc);
        *(float4*)&Hs[h_row][h_q + 4] = *(const float4*)(hsrc + 4);

        float4 wa = *(const float4*)(Wd + w_f * EE + k0 + w_q);
        float4 wb = *(const float4*)(Wd + w_f * EE + k0 + w_q + 4);
        Ws[w_q + 0][w_f] = wa.x;  Ws[w_q + 1][w_f] = wa.y;
        Ws[w_q + 2][w_f] = wa.z;  Ws[w_q + 3][w_f] = wa.w;
        Ws[w_q + 4][w_f] = wb.x;  Ws[w_q + 5][w_f] = wb.y;
        Ws[w_q + 6][w_f] = wb.z;  Ws[w_q + 7][w_f] = wb.w;
        __syncthreads();

        #pragma unroll
        for (int kk = 0; kk < 32; kk++) {
            float4 w4 = *(const float4*)&Ws[kk][tf * 4];
            float a0 = Hs[tm +  0][kk];
            float a1 = Hs[tm + 16][kk];
            float a2 = Hs[tm + 32][kk];
            float a3 = Hs[tm + 48][kk];
            acc[0][0] += a0 * w4.x; acc[0][1] += a0 * w4.y; acc[0][2] += a0 * w4.z; acc[0][3] += a0 * w4.w;
            acc[1][0] += a1 * w4.x; acc[1][1] += a1 * w4.y; acc[1][2] += a1 * w4.z; acc[1][3] += a1 * w4.w;
            acc[2][0] += a2 * w4.x; acc[2][1] += a2 * w4.y; acc[2][2] += a2 * w4.z; acc[2][3] += a2 * w4.w;
            acc[3][0] += a3 * w4.x; acc[3][1] += a3 * w4.y; acc[3][2] += a3 * w4.z; acc[3][3] += a3 * w4.w;
        }
        __syncthreads();
    }

    float b0 = bd[tf * 4 + 0], b1 = bd[tf * 4 + 1], b2 = bd[tf * 4 + 2], b3 = bd[tf * 4 + 3];
    #pragma unroll
    for (int i = 0; i < 4; i++) {
        size_t row = m0 + tm + 16 * i;
        float4 o;
        o.x = acc[i][0] + b0;  o.y = acc[i][1] + b1;
        o.z = acc[i][2] + b2;  o.w = acc[i][3] + b3;
        *(float4*)(out + row * FF + tf * 4) = o;
    }
}

// ---------------- launch ----------------
extern "C" void kernel_launch(void* const* d_in, const int* in_sizes, int n_in,
                              void* d_out, int out_size) {
    const float* x    = (const float*)d_in[0];
    const float* eWih = (const float*)d_in[1];
    const float* eWhh = (const float*)d_in[2];
    const float* ebih = (const float*)d_in[3];
    const float* ebhh = (const float*)d_in[4];
    const float* dWih = (const float*)d_in[5];
    const float* dWhh = (const float*)d_in[6];
    const float* dbih = (const float*)d_in[7];
    const float* dbhh = (const float*)d_in[8];
    const float* Wd   = (const float*)d_in[9];
    const float* bd   = (const float*)d_in[10];
    float* out = (float*)d_out;

    const int smem_bytes = (KENC * WSTR + MB * ASTR) * (int)sizeof(float);  // ~128.5 KB
    cudaFuncSetAttribute(persistent_kernel,
                         cudaFuncAttributeMaxDynamicSharedMemorySize, smem_bytes);

    init_state<<<(BB * EE + 255) / 256, 256>>>();
    pack_weights<<<GG, 256>>>(eWih, eWhh, ebih, ebhh, dWih, dWhh, dbih, dbhh, Wd, bd);
    persistent_kernel<<<NCTA, STH, smem_bytes>>>(x);
    project<<<(TT * BB) / PM, 256>>>(Wd, bd, out);
}

// round 4
// speedup vs baseline: 1.4783x; 1.4783x over previous
#include <cuda_runtime.h>
#include <math.h>

// Problem dims
#define BB   256
#define TT   1024
#define FF   64
#define EE   256
#define GG   1024      // 4*E
#define KENC 320       // F + E
#define KDEC 256       // E (decoder dense composed into Whh)

// Persistent-kernel tiling: CTA = 32 batch x 16 e-units (64 gate cols)
#define NCTA 128
#define STH  128
#define ASTR 36        // As[k][b] row stride (16B-aligned rows)
#define WSTR 66        // Ws[k][c'] row stride (u64-aligned cols)
#define WSTRP 68       // projection W stride (16B-aligned rows)

typedef unsigned long long u64;

// ---------------- device scratch (static: no allocation) ----------------
__device__ float g_h[2][EE * BB];                    // hidden state TRANSPOSED [e][b], ping-pong
__device__ float g_Wenc[GG * KENC];                  // [Wih | Whh] rows, K=320
__device__ float g_benc[GG];                         // bih + bhh
__device__ float g_Wdec[GG * KDEC];                  // dWhh + dWih @ Wd
__device__ float g_bdec[GG];                         // dbih + dbhh + dWih @ bd
__device__ float g_WdT[EE * FF];                     // Wd transposed [e][f]
__device__ float g_HallT[(size_t)TT * EE * BB];      // all h_t, TRANSPOSED [t][e][b] (256 MB)
__device__ unsigned g_arrive;
__device__ volatile unsigned g_gen;

__device__ __forceinline__ float sigmoidf_(float v) { return 1.0f / (1.0f + expf(-v)); }

// ---- packed f32x2 helpers ----
__device__ __forceinline__ u64 pack2_dup(float a) {
    u64 r; unsigned u = __float_as_uint(a);
    asm("mov.b64 %0, {%1, %2};" : "=l"(r) : "r"(u), "r"(u));
    return r;
}
__device__ __forceinline__ u64 pack2(float x, float y) {
    u64 r;
    asm("mov.b64 %0, {%1, %2};" : "=l"(r) : "r"(__float_as_uint(x)), "r"(__float_as_uint(y)));
    return r;
}
__device__ __forceinline__ void fma2(u64& d, u64 a, u64 b) {
    asm("fma.rn.f32x2 %0, %1, %2, %3;" : "=l"(d) : "l"(a), "l"(b), "l"(d));
}
__device__ __forceinline__ float2 unpack2(u64 v) {
    unsigned lo, hi;
    asm("mov.b64 {%0, %1}, %2;" : "=r"(lo), "=r"(hi) : "l"(v));
    float2 r; r.x = __uint_as_float(lo); r.y = __uint_as_float(hi); return r;
}

// ---------------- init ----------------
__global__ void init_state() {
    int i = blockIdx.x * blockDim.x + threadIdx.x;
    if (i < EE * BB) g_h[0][i] = 0.0f;
    if (i == 0) { g_arrive = 0; g_gen = 0; }
}

// ---------------- weight packing / decoder composition ----------------
__global__ void pack_weights(const float* __restrict__ eWih, const float* __restrict__ eWhh,
                             const float* __restrict__ ebih, const float* __restrict__ ebhh,
                             const float* __restrict__ dWih, const float* __restrict__ dWhh,
                             const float* __restrict__ dbih, const float* __restrict__ dbhh,
                             const float* __restrict__ Wd,   const float* __restrict__ bd) {
    int row = blockIdx.x;          // 0..1023 (gate row)
    int tid = threadIdx.x;

    // encoder: concat [Wih | Whh] along K
    for (int k = tid; k < KENC; k += blockDim.x)
        g_Wenc[row * KENC + k] = (k < FF) ? eWih[row * FF + k] : eWhh[row * EE + (k - FF)];

    // decoder: Wcomb = dWhh + dWih @ Wd   (exact: x_t always = h@Wd^T + bd)
    for (int k = tid; k < KDEC; k += blockDim.x) {
        float s = dWhh[row * EE + k];
        #pragma unroll
        for (int f = 0; f < FF; f++) s += dWih[row * FF + f] * Wd[f * EE + k];
        g_Wdec[row * KDEC + k] = s;
    }
    // Wd transposed
    if (row < EE)
        for (int f = tid; f < FF; f += blockDim.x)
            g_WdT[row * FF + f] = Wd[f * EE + row];
    if (tid == 0) {
        g_benc[row] = ebih[row] + ebhh[row];
        float s = dbih[row] + dbhh[row];
        for (int f = 0; f < FF; f++) s += dWih[row * FF + f] * bd[f];
        g_bdec[row] = s;
    }
}

// ---------------- software grid barrier (all 128 CTAs resident) ----------------
__device__ __forceinline__ void grid_sync(unsigned& gen) {
    __threadfence();            // publish this thread's h stores
    __syncthreads();
    if (threadIdx.x == 0) {
        unsigned t = atomicAdd(&g_arrive, 1u);
        if (t == NCTA - 1) {
            g_arrive = 0;
            __threadfence();
            g_gen = gen + 1;    // release
        } else {
            while (g_gen == gen) { }
            __threadfence();    // acquire
        }
    }
    gen++;
    __syncthreads();
}

// ---------------- stage this CTA's 64 W rows into smem, interleaved col order ----
// smem col c':  e = (c'>>1)&15,  gate = 2*(c'>>5) + (c'&1)
// => lane l owns cols {2l, 2l+1} = gates {2*(l>>4), 2*(l>>4)+1} of e = l&15
template<int K>
__device__ __forceinline__ void stage_W(float* Ws, const float* __restrict__ gW, int e0) {
    int tid  = threadIdx.x;
    int cp   = tid >> 1;                 // 0..63 smem col
    int half = tid & 1;
    int gate = 2 * (cp >> 5) + (cp & 1);
    int eloc = (cp >> 1) & 15;
    const float* src = gW + (size_t)(gate * EE + e0 + eloc) * K + half * (K / 2);
    #pragma unroll
    for (int k = 0; k < K / 2; k += 4) {
        float4 v = *(const float4*)(src + k);
        int kk = half * (K / 2) + k;
        Ws[(kk + 0) * WSTR + cp] = v.x;
        Ws[(kk + 1) * WSTR + cp] = v.y;
        Ws[(kk + 2) * WSTR + cp] = v.z;
        Ws[(kk + 3) * WSTR + cp] = v.w;
    }
}

// ---------------- one LSTM step ----------------
// Warp wid: rows [8*wid, 8*wid+8). Lane l: 2 cols (2 gates of e=l&15).
// acc[j][c] = f32x2 over row-pair j (rows 8w+2j, +1), c = gate-in-pair.
template<int K, bool ENC>
__device__ __forceinline__ void do_step(
    const float* __restrict__ Ws, float* __restrict__ As,
    const float* __restrict__ x, int t, int rp,
    int b0, int e0, const float4 b4, float2* __restrict__ cc,
    int hall_t, unsigned& gen)
{
    const float* __restrict__ hr = g_h[rp];
    float*       __restrict__ hw = g_h[rp ^ 1];
    const int tid = threadIdx.x;
    const int wid = tid >> 5;
    const int lid = tid & 31;

    // ---- stage A transposed: As[k][b] ----
    if (ENC) {
        // x slice: As[f][b], conflict-free scalar STS (lanes = distinct b)
        int b  = tid & 31;
        int fc = tid >> 5;                   // 0..3
        const float* xs = x + (size_t)(b0 + b) * (TT * FF) + (size_t)t * FF + fc * 16;
        #pragma unroll
        for (int i = 0; i < 4; i++) {
            float4 v = *(const float4*)(xs + 4 * i);
            int f = fc * 16 + 4 * i;
            As[(f + 0) * ASTR + b] = v.x;
            As[(f + 1) * ASTR + b] = v.y;
            As[(f + 2) * ASTR + b] = v.z;
            As[(f + 3) * ASTR + b] = v.w;
        }
    }
    const int AOFF = ENC ? FF : 0;
    {
        // h: hT[e][b] -> As[AOFF+e][b], coalesced float4 both sides
        int bq  = (tid & 7) * 4;
        int e0r = tid >> 3;                  // 0..15
        #pragma unroll
        for (int m = 0; m < 16; m++) {
            int e = e0r + 16 * m;
            float4 v = __ldcg((const float4*)(hr + e * BB + b0 + bq));
            *(float4*)&As[(AOFF + e) * ASTR + bq] = v;
        }
    }
    __syncthreads();

    // ---- gates GEMM ----
    u64 acc[4][2];
    #pragma unroll
    for (int j = 0; j < 4; j++) { acc[j][0] = 0ull; acc[j][1] = 0ull; }

    const float* __restrict__ arow = As + 8 * wid;
    const float* __restrict__ wrow = Ws + 2 * lid;

    #pragma unroll 4
    for (int k = 0; k < K; k++) {
        float4 a01 = *(const float4*)(arow + k * ASTR);       // rows 8w..8w+3 (broadcast)
        float4 a23 = *(const float4*)(arow + k * ASTR + 4);   // rows 8w+4..8w+7
        float2 wv  = *(const float2*)(wrow + k * WSTR);       // 2 gate cols
        u64 wd0 = pack2_dup(wv.x);
        u64 wd1 = pack2_dup(wv.y);
        u64 A0 = ((const u64*)&a01)[0], A1 = ((const u64*)&a01)[1];
        u64 A2 = ((const u64*)&a23)[0], A3 = ((const u64*)&a23)[1];
        fma2(acc[0][0], A0, wd0);  fma2(acc[0][1], A0, wd1);
        fma2(acc[1][0], A1, wd0);  fma2(acc[1][1], A1, wd1);
        fma2(acc[2][0], A2, wd0);  fma2(acc[2][1], A2, wd1);
        fma2(acc[3][0], A3, wd0);  fma2(acc[3][1], A3, wd1);
    }

    // ---- gate exchange: lanes l & l^16 share e; {i,f} on lo-lanes, {g,o} on hi ----
    const bool lo = (lid < 16);
    u64 gIF[2][2], gGO[2][2];
    #pragma unroll
    for (int j = 0; j < 2; j++) {
        #pragma unroll
        for (int c = 0; c < 2; c++) {
            u64 send = lo ? acc[2 + j][c] : acc[j][c];
            u64 recv = __shfl_xor_sync(0xffffffffu, send, 16);
            gIF[j][c] = lo ? acc[j][c] : recv;       // gates i,f for my 2 row-pairs
            gGO[j][c] = lo ? recv : acc[2 + j][c];   // gates g,o
        }
    }

    // ---- pointwise update; c in registers; h stored transposed ----
    const int eg = e0 + (lid & 15);
    #pragma unroll
    for (int j = 0; j < 2; j++) {
        const int rpair = lo ? j : (2 + j);
        const int r0 = b0 + 8 * wid + 2 * rpair;      // global batch row (even)
        float2 vi = unpack2(gIF[j][0]);
        float2 vf = unpack2(gIF[j][1]);
        float2 vg = unpack2(gGO[j][0]);
        float2 vo = unpack2(gGO[j][1]);
        float ix = sigmoidf_(vi.x + b4.x), iy = sigmoidf_(vi.y + b4.x);
        float fx = sigmoidf_(vf.x + b4.y), fy = sigmoidf_(vf.y + b4.y);
        float gx = tanhf   (vg.x + b4.z), gy = tanhf   (vg.y + b4.z);
        float ox = sigmoidf_(vo.x + b4.w), oy = sigmoidf_(vo.y + b4.w);
        cc[j].x = fx * cc[j].x + ix * gx;
        cc[j].y = fy * cc[j].y + iy * gy;
        float hx = ox * tanhf(cc[j].x);
        float hy = oy * tanhf(cc[j].y);
        u64 hp = pack2(hx, hy);
        *(u64*)(hw + eg * BB + r0) = hp;
        if (hall_t >= 0)
            *(u64*)(g_HallT + ((size_t)hall_t * EE + eg) * BB + r0) = hp;
    }

    grid_sync(gen);
}

// ---------------- the persistent recurrence kernel ----------------
__global__ void __launch_bounds__(STH, 1)
persistent_kernel(const float* __restrict__ x)
{
    extern __shared__ float smem[];
    float* Ws = smem;                        // [K][WSTR], max 320*66
    float* As = smem + KENC * WSTR;          // [320][ASTR]

    const int tid = threadIdx.x;
    const int cta = blockIdx.x;              // 0..127
    const int b0  = (cta & 7) * 32;
    const int e0  = (cta >> 3) * 16;
    const int eg  = e0 + ((tid & 31) & 15);

    unsigned gen = 0;
    float2 cc[2] = {{0.f, 0.f}, {0.f, 0.f}};

    // ===== encoder phase =====
    float4 b4 = make_float4(g_benc[eg], g_benc[EE + eg], g_benc[2 * EE + eg], g_benc[3 * EE + eg]);
    stage_W<KENC>(Ws, g_Wenc, e0);
    __syncthreads();
    for (int t = 0; t < TT; t++)
        do_step<KENC, true>(Ws, As, x, t, t & 1, b0, e0, b4, cc,
                            (t == TT - 1) ? 0 : -1, gen);

    // ===== decoder phase (dense projection composed into Whh) =====
    b4 = make_float4(g_bdec[eg], g_bdec[EE + eg], g_bdec[2 * EE + eg], g_bdec[3 * EE + eg]);
    __syncthreads();
    stage_W<KDEC>(Ws, g_Wdec, e0);
    __syncthreads();
    for (int t = 1; t < TT; t++)
        do_step<KDEC, false>(Ws, As, nullptr, 0, (t - 1) & 1, b0, e0, b4, cc,
                             t, gen);
}

// ---------------- final projection: out[t*B+b][f] = HallT[t][:,b] . WdT[:,f] + bd ----
// Same optimized GEMM shape as the decoder step (32 rows x 64 cols, K=256).
__global__ void __launch_bounds__(STH)
project2(const float* __restrict__ bd, float* __restrict__ out)
{
    extern __shared__ float smem[];
    float* Ws = smem;                        // [256][WSTRP]
    float* As = smem + KDEC * WSTRP;         // [256][ASTR]

    const int tid = threadIdx.x;
    const int wid = tid >> 5;
    const int lid = tid & 31;
    const int t   = blockIdx.x >> 3;
    const int b0  = (blockIdx.x & 7) * 32;

    // stage WdT -> Ws[e][f]
    #pragma unroll
    for (int j = 0; j < 32; j++) {
        int idx = tid + STH * j;             // 0..4095
        int e = idx >> 4, fq = (idx & 15) * 4;
        float4 v = *(const float4*)(g_WdT + e * FF + fq);
        *(float4*)&Ws[e * WSTRP + fq] = v;
    }
    // stage HallT[t] -> As[e][b]
    {
        int bq  = (tid & 7) * 4;
        int e0r = tid >> 3;
        #pragma unroll
        for (int m = 0; m < 16; m++) {
            int e = e0r + 16 * m;
            float4 v = *(const float4*)(g_HallT + ((size_t)t * EE + e) * BB + b0 + bq);
            *(float4*)&As[e * ASTR + bq] = v;
        }
    }
    __syncthreads();

    u64 acc[4][2];
    #pragma unroll
    for (int j = 0; j < 4; j++) { acc[j][0] = 0ull; acc[j][1] = 0ull; }

    const float* __restrict__ arow = As + 8 * wid;
    const float* __restrict__ wrow = Ws + 2 * lid;

    #pragma unroll 4
    for (int k = 0; k < KDEC; k++) {
        float4 a01 = *(const float4*)(arow + k * ASTR);
        float4 a23 = *(const float4*)(arow + k * ASTR + 4);
        float2 wv  = *(const float2*)(wrow + k * WSTRP);
        u64 wd0 = pack2_dup(wv.x);
        u64 wd1 = pack2_dup(wv.y);
        u64 A0 = ((const u64*)&a01)[0], A1 = ((const u64*)&a01)[1];
        u64 A2 = ((const u64*)&a23)[0], A3 = ((const u64*)&a23)[1];
        fma2(acc[0][0], A0, wd0);  fma2(acc[0][1], A0, wd1);
        fma2(acc[1][0], A1, wd0);  fma2(acc[1][1], A1, wd1);
        fma2(acc[2][0], A2, wd0);  fma2(acc[2][1], A2, wd1);
        fma2(acc[3][0], A3, wd0);  fma2(acc[3][1], A3, wd1);
    }

    const float bf0 = bd[2 * lid];
    const float bf1 = bd[2 * lid + 1];
    #pragma unroll
    for (int j = 0; j < 4; j++) {
        int r0 = b0 + 8 * wid + 2 * j;
        float2 v0 = unpack2(acc[j][0]);      // col 2l, rows r0 / r0+1
        float2 v1 = unpack2(acc[j][1]);      // col 2l+1
        size_t row0 = (size_t)t * BB + r0;
        *(u64*)(out + row0 * FF + 2 * lid)        = pack2(v0.x + bf0, v1.x + bf1);
        *(u64*)(out + (row0 + 1) * FF + 2 * lid)  = pack2(v0.y + bf0, v1.y + bf1);
    }
}

// ---------------- launch ----------------
extern "C" void kernel_launch(void* const* d_in, const int* in_sizes, int n_in,
                              void* d_out, int out_size) {
    const float* x    = (const float*)d_in[0];
    const float* eWih = (const float*)d_in[1];
    const float* eWhh = (const float*)d_in[2];
    const float* ebih = (const float*)d_in[3];
    const float* ebhh = (const float*)d_in[4];
    const float* dWih = (const float*)d_in[5];
    const float* dWhh = (const float*)d_in[6];
    const float* dbih = (const float*)d_in[7];
    const float* dbhh = (const float*)d_in[8];
    const float* Wd   = (const float*)d_in[9];
    const float* bd   = (const float*)d_in[10];
    float* out = (float*)d_out;

    const int smem_main = (KENC * WSTR + KENC * ASTR) * (int)sizeof(float);   // ~127.5 KB
    const int smem_proj = (KDEC * WSTRP + KDEC * ASTR) * (int)sizeof(float);  // ~104 KB
    cudaFuncSetAttribute(persistent_kernel, cudaFuncAttributeMaxDynamicSharedMemorySize, smem_main);
    cudaFuncSetAttribute(project2,          cudaFuncAttributeMaxDynamicSharedMemorySize, smem_proj);

    init_state<<<(EE * BB + 255) / 256, 256>>>();
    pack_weights<<<GG, 256>>>(eWih, eWhh, ebih, ebhh, dWih, dWhh, dbih, dbhh, Wd, bd);
    persistent_kernel<<<NCTA, STH, smem_main>>>(x);
    project2<<<(TT * BB) / 32, STH, smem_proj>>>(bd, out);
}

// round 5
// speedup vs baseline: 1.7427x; 1.1789x over previous
#include <cuda_runtime.h>
#include <math.h>

// Problem dims
#define BB   256
#define TT   1024
#define FF   64
#define EE   256
#define GG   1024      // 4*E
#define KENC 320       // F + E
#define KDEC 256       // E (decoder dense composed into Whh)

// Persistent-kernel tiling: CTA = 32 batch x 16 e-units (64 gate cols)
// 256 threads: warps {w, w+4} split K; warp covers 8 batch rows.
#define NCTA 128
#define STH  256
#define GRPS 8         // independent batch groups (16 CTAs each)
#define ASTR 36        // As[k][b] row stride
#define WSTR 66        // Ws[k][c'] row stride
#define WSTRP 68       // projection W stride

typedef unsigned long long u64;

// ---------------- device scratch (static: no allocation) ----------------
__device__ float g_h[2][EE * BB];                    // hidden state TRANSPOSED [e][b], ping-pong
__device__ float g_Wenc[GG * KENC];                  // [Wih | Whh] rows, K=320
__device__ float g_benc[GG];                         // bih + bhh
__device__ float g_Wdec[GG * KDEC];                  // dWhh + dWih @ Wd
__device__ float g_bdec[GG];                         // dbih + dbhh + dWih @ bd
__device__ float g_WdT[EE * FF];                     // Wd transposed [e][f]
__device__ float g_HallT[(size_t)TT * EE * BB];      // all h_t, TRANSPOSED [t][e][b]
__device__ unsigned g_arrive[GRPS * 32];             // per-group arrive counters (128B apart)
__device__ volatile unsigned g_gen[GRPS * 32];       // per-group generation flags

__device__ __forceinline__ float sigmoidf_(float v) { return 1.0f / (1.0f + __expf(-v)); }
__device__ __forceinline__ float tanhf_(float v) {
    float t = __expf(2.0f * v);
    return 1.0f - 2.0f / (t + 1.0f);
}

// ---- packed f32x2 helpers ----
__device__ __forceinline__ u64 pack2_dup(float a) {
    u64 r; unsigned u = __float_as_uint(a);
    asm("mov.b64 %0, {%1, %2};" : "=l"(r) : "r"(u), "r"(u));
    return r;
}
__device__ __forceinline__ u64 pack2(float x, float y) {
    u64 r;
    asm("mov.b64 %0, {%1, %2};" : "=l"(r) : "r"(__float_as_uint(x)), "r"(__float_as_uint(y)));
    return r;
}
__device__ __forceinline__ void fma2(u64& d, u64 a, u64 b) {
    asm("fma.rn.f32x2 %0, %1, %2, %3;" : "=l"(d) : "l"(a), "l"(b), "l"(d));
}
__device__ __forceinline__ u64 add2(u64 a, u64 b) {
    u64 r;
    asm("add.rn.f32x2 %0, %1, %2;" : "=l"(r) : "l"(a), "l"(b));
    return r;
}
__device__ __forceinline__ float2 unpack2(u64 v) {
    unsigned lo, hi;
    asm("mov.b64 {%0, %1}, %2;" : "=r"(lo), "=r"(hi) : "l"(v));
    float2 r; r.x = __uint_as_float(lo); r.y = __uint_as_float(hi); return r;
}

// ---------------- init ----------------
__global__ void init_state() {
    int i = blockIdx.x * blockDim.x + threadIdx.x;
    if (i < EE * BB) g_h[0][i] = 0.0f;
    if (i < GRPS) { g_arrive[i * 32] = 0; g_gen[i * 32] = 0; }
}

// ---------------- weight packing / decoder composition ----------------
__global__ void pack_weights(const float* __restrict__ eWih, const float* __restrict__ eWhh,
                             const float* __restrict__ ebih, const float* __restrict__ ebhh,
                             const float* __restrict__ dWih, const float* __restrict__ dWhh,
                             const float* __restrict__ dbih, const float* __restrict__ dbhh,
                             const float* __restrict__ Wd,   const float* __restrict__ bd) {
    int row = blockIdx.x;          // 0..1023 (gate row)
    int tid = threadIdx.x;

    for (int k = tid; k < KENC; k += blockDim.x)
        g_Wenc[row * KENC + k] = (k < FF) ? eWih[row * FF + k] : eWhh[row * EE + (k - FF)];

    for (int k = tid; k < KDEC; k += blockDim.x) {
        float s = dWhh[row * EE + k];
        #pragma unroll
        for (int f = 0; f < FF; f++) s += dWih[row * FF + f] * Wd[f * EE + k];
        g_Wdec[row * KDEC + k] = s;
    }
    if (row < EE)
        for (int f = tid; f < FF; f += blockDim.x)
            g_WdT[row * FF + f] = Wd[f * EE + row];
    if (tid == 0) {
        g_benc[row] = ebih[row] + ebhh[row];
        float s = dbih[row] + dbhh[row];
        for (int f = 0; f < FF; f++) s += dWih[row * FF + f] * bd[f];
        g_bdec[row] = s;
    }
}

// ---------------- per-group barrier (16 CTAs of one batch group) ----------------
__device__ __forceinline__ void group_sync(unsigned& gen, int grp) {
    __threadfence();            // publish h stores
    __syncthreads();
    if (threadIdx.x == 0) {
        unsigned* arr = &g_arrive[grp * 32];
        volatile unsigned* flg = &g_gen[grp * 32];
        unsigned t = atomicAdd(arr, 1u);
        if (t == 15u) {
            *arr = 0;
            __threadfence();
            *flg = gen + 1;     // release
        } else {
            while (*flg == gen) { }
            __threadfence();    // acquire
        }
    }
    gen++;
    __syncthreads();
}

// ---------------- stage this CTA's 64 W rows into smem, interleaved col order ----
// smem col c':  e = (c'>>1)&15,  gate = 2*(c'>>5) + (c'&1)
template<int K>
__device__ __forceinline__ void stage_W(float* Ws, const float* __restrict__ gW, int e0) {
    int tid  = threadIdx.x;
    int cp   = tid >> 2;                 // 0..63 smem col
    int q    = tid & 3;                  // K quarter
    int gate = 2 * (cp >> 5) + (cp & 1);
    int eloc = (cp >> 1) & 15;
    const float* src = gW + (size_t)(gate * EE + e0 + eloc) * K + q * (K / 4);
    #pragma unroll
    for (int k = 0; k < K / 4; k += 4) {
        float4 v = *(const float4*)(src + k);
        int kk = q * (K / 4) + k;
        Ws[(kk + 0) * WSTR + cp] = v.x;
        Ws[(kk + 1) * WSTR + cp] = v.y;
        Ws[(kk + 2) * WSTR + cp] = v.z;
        Ws[(kk + 3) * WSTR + cp] = v.w;
    }
}

// ---------------- one LSTM step ----------------
// warps {w, w+4}: rows [8*(w&3), +8), K halves. Lane l: cols {2l,2l+1}
// = gates {i,f} (l<16) / {g,o} (l>=16) of e = l&15.
template<int K, bool ENC>
__device__ __forceinline__ void do_step(
    const float* __restrict__ Ws, float* __restrict__ As, u64* __restrict__ scratch,
    const float* __restrict__ x, int t, int rp,
    int b0, int e0, const float4 b4, float2* __restrict__ cc,
    int hall_t, unsigned& gen, int grp)
{
    const float* __restrict__ hr = g_h[rp];
    float*       __restrict__ hw = g_h[rp ^ 1];
    const int tid  = threadIdx.x;
    const int w    = tid >> 5;
    const int lid  = tid & 31;
    const int wr   = w & 3;
    const int half = w >> 2;

    // ---- stage A transposed: As[k][b] ----
    if (ENC) {
        // x slice: As[f][b]; thread (b=lid, chunk=w) loads 8 f, scalar STS
        const float* xs = x + (size_t)(b0 + lid) * (TT * FF) + (size_t)t * FF + w * 8;
        float4 v0 = *(const float4*)(xs);
        float4 v1 = *(const float4*)(xs + 4);
        int f = w * 8;
        As[(f + 0) * ASTR + lid] = v0.x;  As[(f + 1) * ASTR + lid] = v0.y;
        As[(f + 2) * ASTR + lid] = v0.z;  As[(f + 3) * ASTR + lid] = v0.w;
        As[(f + 4) * ASTR + lid] = v1.x;  As[(f + 5) * ASTR + lid] = v1.y;
        As[(f + 6) * ASTR + lid] = v1.z;  As[(f + 7) * ASTR + lid] = v1.w;
    }
    const int AOFF = ENC ? FF : 0;
    {
        // h: hT[e][b0..b0+32) -> As[AOFF+e][:], float4 both sides
        int bq = (tid & 7) * 4;
        int er = tid >> 3;                   // 0..31
        #pragma unroll
        for (int m = 0; m < 8; m++) {
            int e = er + 32 * m;
            float4 v = __ldcg((const float4*)(hr + e * BB + b0 + bq));
            *(float4*)&As[(AOFF + e) * ASTR + bq] = v;
        }
    }
    __syncthreads();

    // ---- gates GEMM (this warp's K half) ----
    u64 acc[4][2];
    #pragma unroll
    for (int j = 0; j < 4; j++) { acc[j][0] = 0ull; acc[j][1] = 0ull; }

    const float* __restrict__ ap = As + 8 * wr + half * (K / 2) * ASTR;
    const float* __restrict__ wp = Ws + 2 * lid + half * (K / 2) * WSTR;

    #pragma unroll 4
    for (int k = 0; k < K / 2; k++) {
        float4 a01 = *(const float4*)(ap + k * ASTR);       // rows 8wr..+3 (broadcast)
        float4 a23 = *(const float4*)(ap + k * ASTR + 4);   // rows 8wr+4..+7
        float2 wv  = *(const float2*)(wp + k * WSTR);       // 2 gate cols
        u64 wd0 = pack2_dup(wv.x);
        u64 wd1 = pack2_dup(wv.y);
        u64 A0 = ((const u64*)&a01)[0], A1 = ((const u64*)&a01)[1];
        u64 A2 = ((const u64*)&a23)[0], A3 = ((const u64*)&a23)[1];
        fma2(acc[0][0], A0, wd0);  fma2(acc[0][1], A0, wd1);
        fma2(acc[1][0], A1, wd0);  fma2(acc[1][1], A1, wd1);
        fma2(acc[2][0], A2, wd0);  fma2(acc[2][1], A2, wd1);
        fma2(acc[3][0], A3, wd0);  fma2(acc[3][1], A3, wd1);
    }

    // ---- combine K halves: hi warps dump partials, lo warps add ----
    if (half) {
        #pragma unroll
        for (int j = 0; j < 4; j++) {
            scratch[(j * 2 + 0) * 128 + wr * 32 + lid] = acc[j][0];
            scratch[(j * 2 + 1) * 128 + wr * 32 + lid] = acc[j][1];
        }
    }
    __syncthreads();

    if (!half) {
        #pragma unroll
        for (int j = 0; j < 4; j++) {
            acc[j][0] = add2(acc[j][0], scratch[(j * 2 + 0) * 128 + wr * 32 + lid]);
            acc[j][1] = add2(acc[j][1], scratch[(j * 2 + 1) * 128 + wr * 32 + lid]);
        }

        // ---- gate exchange: lanes l & l^16 share e ----
        const bool lo = (lid < 16);
        u64 gIF[2][2], gGO[2][2];
        #pragma unroll
        for (int j = 0; j < 2; j++) {
            #pragma unroll
            for (int c = 0; c < 2; c++) {
                u64 send = lo ? acc[2 + j][c] : acc[j][c];
                u64 recv = __shfl_xor_sync(0xffffffffu, send, 16);
                gIF[j][c] = lo ? acc[j][c] : recv;
                gGO[j][c] = lo ? recv : acc[2 + j][c];
            }
        }

        // ---- pointwise update; c in registers; h stored transposed ----
        const int eg = e0 + (lid & 15);
        #pragma unroll
        for (int j = 0; j < 2; j++) {
            const int rpair = lo ? j : (2 + j);
            const int r0 = b0 + 8 * wr + 2 * rpair;
            float2 vi = unpack2(gIF[j][0]);
            float2 vf = unpack2(gIF[j][1]);
            float2 vg = unpack2(gGO[j][0]);
            float2 vo = unpack2(gGO[j][1]);
            float ix = sigmoidf_(vi.x + b4.x), iy = sigmoidf_(vi.y + b4.x);
            float fx = sigmoidf_(vf.x + b4.y), fy = sigmoidf_(vf.y + b4.y);
            float gx = tanhf_  (vg.x + b4.z), gy = tanhf_  (vg.y + b4.z);
            float ox = sigmoidf_(vo.x + b4.w), oy = sigmoidf_(vo.y + b4.w);
            cc[j].x = fx * cc[j].x + ix * gx;
            cc[j].y = fy * cc[j].y + iy * gy;
            float hx = ox * tanhf_(cc[j].x);
            float hy = oy * tanhf_(cc[j].y);
            u64 hp = pack2(hx, hy);
            *(u64*)(hw + eg * BB + r0) = hp;
            if (hall_t >= 0)
                *(u64*)(g_HallT + ((size_t)hall_t * EE + eg) * BB + r0) = hp;
        }
    }

    group_sync(gen, grp);
}

// ---------------- the persistent recurrence kernel ----------------
__global__ void __launch_bounds__(STH, 1)
persistent_kernel(const float* __restrict__ x)
{
    extern __shared__ float smem[];
    float* Ws = smem;                                   // [K][WSTR]
    float* As = smem + KENC * WSTR;                     // [320][ASTR]
    u64*  scratch = (u64*)(smem + KENC * WSTR + KENC * ASTR);  // 1024 u64

    const int tid = threadIdx.x;
    const int cta = blockIdx.x;              // 0..127
    const int grp = cta & 7;                 // batch group (independent!)
    const int b0  = grp * 32;
    const int e0  = (cta >> 3) * 16;
    const int eg  = e0 + (tid & 15);

    unsigned gen = 0;
    float2 cc[2] = {{0.f, 0.f}, {0.f, 0.f}};

    // ===== encoder phase =====
    float4 b4 = make_float4(g_benc[eg], g_benc[EE + eg], g_benc[2 * EE + eg], g_benc[3 * EE + eg]);
    stage_W<KENC>(Ws, g_Wenc, e0);
    __syncthreads();
    for (int t = 0; t < TT; t++)
        do_step<KENC, true>(Ws, As, scratch, x, t, t & 1, b0, e0, b4, cc,
                            (t == TT - 1) ? 0 : -1, gen, grp);

    // ===== decoder phase (dense projection composed into Whh) =====
    b4 = make_float4(g_bdec[eg], g_bdec[EE + eg], g_bdec[2 * EE + eg], g_bdec[3 * EE + eg]);
    __syncthreads();
    stage_W<KDEC>(Ws, g_Wdec, e0);
    __syncthreads();
    for (int t = 1; t < TT; t++)
        do_step<KDEC, false>(Ws, As, scratch, nullptr, 0, (t - 1) & 1, b0, e0, b4, cc,
                             t, gen, grp);
}

// ---------------- final projection: out[t*B+b][f] = HallT[t][:,b] . WdT[:,f] + bd ----
__global__ void __launch_bounds__(128)
project2(const float* __restrict__ bd, float* __restrict__ out)
{
    extern __shared__ float smem[];
    float* Ws = smem;                        // [256][WSTRP]
    float* As = smem + KDEC * WSTRP;         // [256][ASTR]

    const int tid = threadIdx.x;
    const int wid = tid >> 5;
    const int lid = tid & 31;
    const int t   = blockIdx.x >> 3;
    const int b0  = (blockIdx.x & 7) * 32;

    #pragma unroll
    for (int j = 0; j < 32; j++) {
        int idx = tid + 128 * j;             // 0..4095
        int e = idx >> 4, fq = (idx & 15) * 4;
        float4 v = *(const float4*)(g_WdT + e * FF + fq);
        *(float4*)&Ws[e * WSTRP + fq] = v;
    }
    {
        int bq = (tid & 7) * 4;
        int er = tid >> 3;
        #pragma unroll
        for (int m = 0; m < 16; m++) {
            int e = er + 16 * m;
            float4 v = *(const float4*)(g_HallT + ((size_t)t * EE + e) * BB + b0 + bq);
            *(float4*)&As[e * ASTR + bq] = v;
        }
    }
    __syncthreads();

    u64 acc[4][2];
    #pragma unroll
    for (int j = 0; j < 4; j++) { acc[j][0] = 0ull; acc[j][1] = 0ull; }

    const float* __restrict__ arow = As + 8 * wid;
    const float* __restrict__ wrow = Ws + 2 * lid;

    #pragma unroll 4
    for (int k = 0; k < KDEC; k++) {
        float4 a01 = *(const float4*)(arow + k * ASTR);
        float4 a23 = *(const float4*)(arow + k * ASTR + 4);
        float2 wv  = *(const float2*)(wrow + k * WSTRP);
        u64 wd0 = pack2_dup(wv.x);
        u64 wd1 = pack2_dup(wv.y);
        u64 A0 = ((const u64*)&a01)[0], A1 = ((const u64*)&a01)[1];
        u64 A2 = ((const u64*)&a23)[0], A3 = ((const u64*)&a23)[1];
        fma2(acc[0][0], A0, wd0);  fma2(acc[0][1], A0, wd1);
        fma2(acc[1][0], A1, wd0);  fma2(acc[1][1], A1, wd1);
        fma2(acc[2][0], A2, wd0);  fma2(acc[2][1], A2, wd1);
        fma2(acc[3][0], A3, wd0);  fma2(acc[3][1], A3, wd1);
    }

    const float bf0 = bd[2 * lid];
    const float bf1 = bd[2 * lid + 1];
    #pragma unroll
    for (int j = 0; j < 4; j++) {
        int r0 = b0 + 8 * wid + 2 * j;
        float2 v0 = unpack2(acc[j][0]);
        float2 v1 = unpack2(acc[j][1]);
        size_t row0 = (size_t)t * BB + r0;
        *(u64*)(out + row0 * FF + 2 * lid)        = pack2(v0.x + bf0, v1.x + bf1);
        *(u64*)(out + (row0 + 1) * FF + 2 * lid)  = pack2(v0.y + bf0, v1.y + bf1);
    }
}

// ---------------- launch ----------------
extern "C" void kernel_launch(void* const* d_in, const int* in_sizes, int n_in,
                              void* d_out, int out_size) {
    const float* x    = (const float*)d_in[0];
    const float* eWih = (const float*)d_in[1];
    const float* eWhh = (const float*)d_in[2];
    const float* ebih = (const float*)d_in[3];
    const float* ebhh = (const float*)d_in[4];
    const float* dWih = (const float*)d_in[5];
    const float* dWhh = (const float*)d_in[6];
    const float* dbih = (const float*)d_in[7];
    const float* dbhh = (const float*)d_in[8];
    const float* Wd   = (const float*)d_in[9];
    const float* bd   = (const float*)d_in[10];
    float* out = (float*)d_out;

    const int smem_main = (KENC * WSTR + KENC * ASTR) * (int)sizeof(float) + 1024 * (int)sizeof(u64);
    const int smem_proj = (KDEC * WSTRP + KDEC * ASTR) * (int)sizeof(float);
    cudaFuncSetAttribute(persistent_kernel, cudaFuncAttributeMaxDynamicSharedMemorySize, smem_main);
    cudaFuncSetAttribute(project2,          cudaFuncAttributeMaxDynamicSharedMemorySize, smem_proj);

    init_state<<<(EE * BB + 255) / 256, 256>>>();
    pack_weights<<<GG, 256>>>(eWih, eWhh, ebih, ebhh, dWih, dWhh, dbih, dbhh, Wd, bd);
    persistent_kernel<<<NCTA, STH, smem_main>>>(x);
    project2<<<(TT * BB) / 32, 128, smem_proj>>>(bd, out);
}

// round 6
// speedup vs baseline: 1.7441x; 1.0008x over previous
#include <cuda_runtime.h>
#include <math.h>

// Problem dims
#define BB   256
#define TT   1024
#define FF   64
#define EE   256
#define GG   1024      // 4*E
#define KENC 320       // F + E
#define KDEC 256       // E (decoder dense composed into Whh)

// Persistent-kernel tiling: CTA = 32 batch x 16 e-units (64 gate cols)
// 256 threads: warps {w, w+4} split K; warp covers 8 batch rows.
#define NCTA 128
#define STH  256
#define GRPS 8         // independent batch groups (16 CTAs each)
#define ASTR 36        // As[k][b] row stride
#define WSTR 66        // Ws[k][c'] row stride
#define WSTRP 68       // projection W stride

typedef unsigned long long u64;

// ---------------- device scratch (static: no allocation) ----------------
__device__ float g_h[2][EE * BB];                    // hidden state TRANSPOSED [e][b], ping-pong
__device__ float g_Wenc[GG * KENC];                  // [Wih | Whh] rows, K=320
__device__ float g_benc[GG];                         // bih + bhh
__device__ float g_Wdec[GG * KDEC];                  // dWhh + dWih @ Wd
__device__ float g_bdec[GG];                         // dbih + dbhh + dWih @ bd
__device__ float g_WdT[EE * FF];                     // Wd transposed [e][f]
__device__ float g_HallT[(size_t)TT * EE * BB];      // all h_t, TRANSPOSED [t][e][b]
__device__ unsigned g_arrive[GRPS * 32];             // per-group arrive counters (128B apart)
__device__ volatile unsigned g_gen[GRPS * 32];       // per-group generation flags

__device__ __forceinline__ float sigmoidf_(float v) { return 1.0f / (1.0f + __expf(-v)); }
__device__ __forceinline__ float tanhf_(float v) {
    float t = __expf(2.0f * v);
    return 1.0f - 2.0f / (t + 1.0f);
}

// ---- packed f32x2 helpers ----
__device__ __forceinline__ u64 pack2_dup(float a) {
    u64 r; unsigned u = __float_as_uint(a);
    asm("mov.b64 %0, {%1, %2};" : "=l"(r) : "r"(u), "r"(u));
    return r;
}
__device__ __forceinline__ u64 pack2(float x, float y) {
    u64 r;
    asm("mov.b64 %0, {%1, %2};" : "=l"(r) : "r"(__float_as_uint(x)), "r"(__float_as_uint(y)));
    return r;
}
__device__ __forceinline__ void fma2(u64& d, u64 a, u64 b) {
    asm("fma.rn.f32x2 %0, %1, %2, %3;" : "=l"(d) : "l"(a), "l"(b), "l"(d));
}
__device__ __forceinline__ u64 add2(u64 a, u64 b) {
    u64 r;
    asm("add.rn.f32x2 %0, %1, %2;" : "=l"(r) : "l"(a), "l"(b));
    return r;
}
__device__ __forceinline__ float2 unpack2(u64 v) {
    unsigned lo, hi;
    asm("mov.b64 {%0, %1}, %2;" : "=r"(lo), "=r"(hi) : "l"(v));
    float2 r; r.x = __uint_as_float(lo); r.y = __uint_as_float(hi); return r;
}

// ---------------- init ----------------
__global__ void init_state() {
    int i = blockIdx.x * blockDim.x + threadIdx.x;
    if (i < EE * BB) g_h[0][i] = 0.0f;
    if (i < GRPS) { g_arrive[i * 32] = 0; g_gen[i * 32] = 0; }
}

// ---------------- weight packing / decoder composition ----------------
__global__ void pack_weights(const float* __restrict__ eWih, const float* __restrict__ eWhh,
                             const float* __restrict__ ebih, const float* __restrict__ ebhh,
                             const float* __restrict__ dWih, const float* __restrict__ dWhh,
                             const float* __restrict__ dbih, const float* __restrict__ dbhh,
                             const float* __restrict__ Wd,   const float* __restrict__ bd) {
    int row = blockIdx.x;          // 0..1023 (gate row)
    int tid = threadIdx.x;

    for (int k = tid; k < KENC; k += blockDim.x)
        g_Wenc[row * KENC + k] = (k < FF) ? eWih[row * FF + k] : eWhh[row * EE + (k - FF)];

    for (int k = tid; k < KDEC; k += blockDim.x) {
        float s = dWhh[row * EE + k];
        #pragma unroll
        for (int f = 0; f < FF; f++) s += dWih[row * FF + f] * Wd[f * EE + k];
        g_Wdec[row * KDEC + k] = s;
    }
    if (row < EE)
        for (int f = tid; f < FF; f += blockDim.x)
            g_WdT[row * FF + f] = Wd[f * EE + row];
    if (tid == 0) {
        g_benc[row] = ebih[row] + ebhh[row];
        float s = dbih[row] + dbhh[row];
        for (int f = 0; f < FF; f++) s += dWih[row * FF + f] * bd[f];
        g_bdec[row] = s;
    }
}

// ---------------- per-group barrier (16 CTAs of one batch group) ----------------
__device__ __forceinline__ void group_sync(unsigned& gen, int grp) {
    __threadfence();            // publish h stores
    __syncthreads();
    if (threadIdx.x == 0) {
        unsigned* arr = &g_arrive[grp * 32];
        volatile unsigned* flg = &g_gen[grp * 32];
        unsigned t = atomicAdd(arr, 1u);
        if (t == 15u) {
            *arr = 0;
            __threadfence();
            *flg = gen + 1;     // release
        } else {
            while (*flg == gen) { }
            __threadfence();    // acquire
        }
    }
    gen++;
    __syncthreads();
}

// ---------------- stage this CTA's 64 W rows into smem, interleaved col order ----
// smem col c':  e = (c'>>1)&15,  gate = 2*(c'>>5) + (c'&1)
template<int K>
__device__ __forceinline__ void stage_W(float* Ws, const float* __restrict__ gW, int e0) {
    int tid  = threadIdx.x;
    int cp   = tid >> 2;                 // 0..63 smem col
    int q    = tid & 3;                  // K quarter
    int gate = 2 * (cp >> 5) + (cp & 1);
    int eloc = (cp >> 1) & 15;
    const float* src = gW + (size_t)(gate * EE + e0 + eloc) * K + q * (K / 4);
    #pragma unroll
    for (int k = 0; k < K / 4; k += 4) {
        float4 v = *(const float4*)(src + k);
        int kk = q * (K / 4) + k;
        Ws[(kk + 0) * WSTR + cp] = v.x;
        Ws[(kk + 1) * WSTR + cp] = v.y;
        Ws[(kk + 2) * WSTR + cp] = v.z;
        Ws[(kk + 3) * WSTR + cp] = v.w;
    }
}

// ---------------- one LSTM step ----------------
// warps {w, w+4}: rows [8*(w&3), +8), K halves. Lane l: cols {2l,2l+1}
// = gates {i,f} (l<16) / {g,o} (l>=16) of e = l&15.
template<int K, bool ENC>
__device__ __forceinline__ void do_step(
    const float* __restrict__ Ws, float* __restrict__ As, u64* __restrict__ scratch,
    const float* __restrict__ x, int t, int rp,
    int b0, int e0, const float4 b4, float2* __restrict__ cc,
    int hall_t, unsigned& gen, int grp)
{
    const float* __restrict__ hr = g_h[rp];
    float*       __restrict__ hw = g_h[rp ^ 1];
    const int tid  = threadIdx.x;
    const int w    = tid >> 5;
    const int lid  = tid & 31;
    const int wr   = w & 3;
    const int half = w >> 2;

    // ---- stage A transposed: As[k][b] ----
    if (ENC) {
        // x slice: As[f][b]; thread (b=lid, chunk=w) loads 8 f, scalar STS
        const float* xs = x + (size_t)(b0 + lid) * (TT * FF) + (size_t)t * FF + w * 8;
        float4 v0 = *(const float4*)(xs);
        float4 v1 = *(const float4*)(xs + 4);
        int f = w * 8;
        As[(f + 0) * ASTR + lid] = v0.x;  As[(f + 1) * ASTR + lid] = v0.y;
        As[(f + 2) * ASTR + lid] = v0.z;  As[(f + 3) * ASTR + lid] = v0.w;
        As[(f + 4) * ASTR + lid] = v1.x;  As[(f + 5) * ASTR + lid] = v1.y;
        As[(f + 6) * ASTR + lid] = v1.z;  As[(f + 7) * ASTR + lid] = v1.w;
    }
    const int AOFF = ENC ? FF : 0;
    {
        // h: hT[e][b0..b0+32) -> As[AOFF+e][:], float4 both sides
        int bq = (tid & 7) * 4;
        int er = tid >> 3;                   // 0..31
        #pragma unroll
        for (int m = 0; m < 8; m++) {
            int e = er + 32 * m;
            float4 v = __ldcg((const float4*)(hr + e * BB + b0 + bq));
            *(float4*)&As[(AOFF + e) * ASTR + bq] = v;
        }
    }
    __syncthreads();

    // ---- gates GEMM (this warp's K half) ----
    u64 acc[4][2];
    #pragma unroll
    for (int j = 0; j < 4; j++) { acc[j][0] = 0ull; acc[j][1] = 0ull; }

    const float* __restrict__ ap = As + 8 * wr + half * (K / 2) * ASTR;
    const float* __restrict__ wp = Ws + 2 * lid + half * (K / 2) * WSTR;

    #pragma unroll 4
    for (int k = 0; k < K / 2; k++) {
        float4 a01 = *(const float4*)(ap + k * ASTR);       // rows 8wr..+3 (broadcast)
        float4 a23 = *(const float4*)(ap + k * ASTR + 4);   // rows 8wr+4..+7
        float2 wv  = *(const float2*)(wp + k * WSTR);       // 2 gate cols
        u64 wd0 = pack2_dup(wv.x);
        u64 wd1 = pack2_dup(wv.y);
        u64 A0 = ((const u64*)&a01)[0], A1 = ((const u64*)&a01)[1];
        u64 A2 = ((const u64*)&a23)[0], A3 = ((const u64*)&a23)[1];
        fma2(acc[0][0], A0, wd0);  fma2(acc[0][1], A0, wd1);
        fma2(acc[1][0], A1, wd0);  fma2(acc[1][1], A1, wd1);
        fma2(acc[2][0], A2, wd0);  fma2(acc[2][1], A2, wd1);
        fma2(acc[3][0], A3, wd0);  fma2(acc[3][1], A3, wd1);
    }

    // ---- combine K halves: hi warps dump partials, lo warps add ----
    if (half) {
        #pragma unroll
        for (int j = 0; j < 4; j++) {
            scratch[(j * 2 + 0) * 128 + wr * 32 + lid] = acc[j][0];
            scratch[(j * 2 + 1) * 128 + wr * 32 + lid] = acc[j][1];
        }
    }
    __syncthreads();

    if (!half) {
        #pragma unroll
        for (int j = 0; j < 4; j++) {
            acc[j][0] = add2(acc[j][0], scratch[(j * 2 + 0) * 128 + wr * 32 + lid]);
            acc[j][1] = add2(acc[j][1], scratch[(j * 2 + 1) * 128 + wr * 32 + lid]);
        }

        // ---- gate exchange: lanes l & l^16 share e ----
        const bool lo = (lid < 16);
        u64 gIF[2][2], gGO[2][2];
        #pragma unroll
        for (int j = 0; j < 2; j++) {
            #pragma unroll
            for (int c = 0; c < 2; c++) {
                u64 send = lo ? acc[2 + j][c] : acc[j][c];
                u64 recv = __shfl_xor_sync(0xffffffffu, send, 16);
                gIF[j][c] = lo ? acc[j][c] : recv;
                gGO[j][c] = lo ? recv : acc[2 + j][c];
            }
        }

        // ---- pointwise update; c in registers; h stored transposed ----
        const int eg = e0 + (lid & 15);
        #pragma unroll
        for (int j = 0; j < 2; j++) {
            const int rpair = lo ? j : (2 + j);
            const int r0 = b0 + 8 * wr + 2 * rpair;
            float2 vi = unpack2(gIF[j][0]);
            float2 vf = unpack2(gIF[j][1]);
            float2 vg = unpack2(gGO[j][0]);
            float2 vo = unpack2(gGO[j][1]);
            float ix = sigmoidf_(vi.x + b4.x), iy = sigmoidf_(vi.y + b4.x);
            float fx = sigmoidf_(vf.x + b4.y), fy = sigmoidf_(vf.y + b4.y);
            float gx = tanhf_  (vg.x + b4.z), gy = tanhf_  (vg.y + b4.z);
            float ox = sigmoidf_(vo.x + b4.w), oy = sigmoidf_(vo.y + b4.w);
            cc[j].x = fx * cc[j].x + ix * gx;
            cc[j].y = fy * cc[j].y + iy * gy;
            float hx = ox * tanhf_(cc[j].x);
            float hy = oy * tanhf_(cc[j].y);
            u64 hp = pack2(hx, hy);
            *(u64*)(hw + eg * BB + r0) = hp;
            if (hall_t >= 0)
                *(u64*)(g_HallT + ((size_t)hall_t * EE + eg) * BB + r0) = hp;
        }
    }

    group_sync(gen, grp);
}

// ---------------- the persistent recurrence kernel ----------------
__global__ void __launch_bounds__(STH, 1)
persistent_kernel(const float* __restrict__ x)
{
    extern __shared__ float smem[];
    float* Ws = smem;                                   // [K][WSTR]
    float* As = smem + KENC * WSTR;                     // [320][ASTR]
    u64*  scratch = (u64*)(smem + KENC * WSTR + KENC * ASTR);  // 1024 u64

    const int tid = threadIdx.x;
    const int cta = blockIdx.x;              // 0..127
    const int grp = cta & 7;                 // batch group (independent!)
    const int b0  = grp * 32;
    const int e0  = (cta >> 3) * 16;
    const int eg  = e0 + (tid & 15);

    unsigned gen = 0;
    float2 cc[2] = {{0.f, 0.f}, {0.f, 0.f}};

    // ===== encoder phase =====
    float4 b4 = make_float4(g_benc[eg], g_benc[EE + eg], g_benc[2 * EE + eg], g_benc[3 * EE + eg]);
    stage_W<KENC>(Ws, g_Wenc, e0);
    __syncthreads();
    for (int t = 0; t < TT; t++)
        do_step<KENC, true>(Ws, As, scratch, x, t, t & 1, b0, e0, b4, cc,
                            (t == TT - 1) ? 0 : -1, gen, grp);

    // ===== decoder phase (dense projection composed into Whh) =====
    b4 = make_float4(g_bdec[eg], g_bdec[EE + eg], g_bdec[2 * EE + eg], g_bdec[3 * EE + eg]);
    __syncthreads();
    stage_W<KDEC>(Ws, g_Wdec, e0);
    __syncthreads();
    for (int t = 1; t < TT; t++)
        do_step<KDEC, false>(Ws, As, scratch, nullptr, 0, (t - 1) & 1, b0, e0, b4, cc,
                             t, gen, grp);
}

// ---------------- final projection: out[t*B+b][f] = HallT[t][:,b] . WdT[:,f] + bd ----
__global__ void __launch_bounds__(128)
project2(const float* __restrict__ bd, float* __restrict__ out)
{
    extern __shared__ float smem[];
    float* Ws = smem;                        // [256][WSTRP]
    float* As = smem + KDEC * WSTRP;         // [256][ASTR]

    const int tid = threadIdx.x;
    const int wid = tid >> 5;
    const int lid = tid & 31;
    const int t   = blockIdx.x >> 3;
    const int b0  = (blockIdx.x & 7) * 32;

    #pragma unroll
    for (int j = 0; j < 32; j++) {
        int idx = tid + 128 * j;             // 0..4095
        int e = idx >> 4, fq = (idx & 15) * 4;
        float4 v = *(const float4*)(g_WdT + e * FF + fq);
        *(float4*)&Ws[e * WSTRP + fq] = v;
    }
    {
        int bq = (tid & 7) * 4;
        int er = tid >> 3;
        #pragma unroll
        for (int m = 0; m < 16; m++) {
            int e = er + 16 * m;
            float4 v = *(const float4*)(g_HallT + ((size_t)t * EE + e) * BB + b0 + bq);
            *(float4*)&As[e * ASTR + bq] = v;
        }
    }
    __syncthreads();

    u64 acc[4][2];
    #pragma unroll
    for (int j = 0; j < 4; j++) { acc[j][0] = 0ull; acc[j][1] = 0ull; }

    const float* __restrict__ arow = As + 8 * wid;
    const float* __restrict__ wrow = Ws + 2 * lid;

    #pragma unroll 4
    for (int k = 0; k < KDEC; k++) {
        float4 a01 = *(const float4*)(arow + k * ASTR);
        float4 a23 = *(const float4*)(arow + k * ASTR + 4);
        float2 wv  = *(const float2*)(wrow + k * WSTRP);
        u64 wd0 = pack2_dup(wv.x);
        u64 wd1 = pack2_dup(wv.y);
        u64 A0 = ((const u64*)&a01)[0], A1 = ((const u64*)&a01)[1];
        u64 A2 = ((const u64*)&a23)[0], A3 = ((const u64*)&a23)[1];
        fma2(acc[0][0], A0, wd0);  fma2(acc[0][1], A0, wd1);
        fma2(acc[1][0], A1, wd0);  fma2(acc[1][1], A1, wd1);
        fma2(acc[2][0], A2, wd0);  fma2(acc[2][1], A2, wd1);
        fma2(acc[3][0], A3, wd0);  fma2(acc[3][1], A3, wd1);
    }

    const float bf0 = bd[2 * lid];
    const float bf1 = bd[2 * lid + 1];
    #pragma unroll
    for (int j = 0; j < 4; j++) {
        int r0 = b0 + 8 * wid + 2 * j;
        float2 v0 = unpack2(acc[j][0]);
        float2 v1 = unpack2(acc[j][1]);
        size_t row0 = (size_t)t * BB + r0;
        *(u64*)(out + row0 * FF + 2 * lid)        = pack2(v0.x + bf0, v1.x + bf1);
        *(u64*)(out + (row0 + 1) * FF + 2 * lid)  = pack2(v0.y + bf0, v1.y + bf1);
    }
}

// ---------------- launch ----------------
extern "C" void kernel_launch(void* const* d_in, const int* in_sizes, int n_in,
                              void* d_out, int out_size) {
    const float* x    = (const float*)d_in[0];
    const float* eWih = (const float*)d_in[1];
    const float* eWhh = (const float*)d_in[2];
    const float* ebih = (const float*)d_in[3];
    const float* ebhh = (const float*)d_in[4];
    const float* dWih = (const float*)d_in[5];
    const float* dWhh = (const float*)d_in[6];
    const float* dbih = (const float*)d_in[7];
    const float* dbhh = (const float*)d_in[8];
    const float* Wd   = (const float*)d_in[9];
    const float* bd   = (const float*)d_in[10];
    float* out = (float*)d_out;

    const int smem_main = (KENC * WSTR + KENC * ASTR) * (int)sizeof(float) + 1024 * (int)sizeof(u64);
    const int smem_proj = (KDEC * WSTRP + KDEC * ASTR) * (int)sizeof(float);
    cudaFuncSetAttribute(persistent_kernel, cudaFuncAttributeMaxDynamicSharedMemorySize, smem_main);
    cudaFuncSetAttribute(project2,          cudaFuncAttributeMaxDynamicSharedMemorySize, smem_proj);

    init_state<<<(EE * BB + 255) / 256, 256>>>();
    pack_weights<<<GG, 256>>>(eWih, eWhh, ebih, ebhh, dWih, dWhh, dbih, dbhh, Wd, bd);
    persistent_kernel<<<NCTA, STH, smem_main>>>(x);
    project2<<<(TT * BB) / 32, 128, smem_proj>>>(bd, out);
}